// round 1
// baseline (speedup 1.0000x reference)
#include <cuda_runtime.h>

// Problem constants: x [R=128, C=256, B=1, E=768], H=12, DK=64
#define OUT_ELEMS   25165824L   // 128*256*768
#define PROBS_ELEMS 50331648L   // 12*256*128*128

// Scratch (allocation-free rule: device globals)
__device__ float g_q[25165824];
__device__ float g_k[25165824];
__device__ float g_v[25165824];
__device__ float g_ctx[25165824];

// ---------------------------------------------------------------------------
// NT-GEMM with bias + scale:  C[m,n] = (sum_k A[m,k] * B[n,k] + bias[n]) * scale
// A: [M,K] row-major, B: [N,K] row-major (torch-style [out,in] weight)
// BM=BN=128, BK=16, 256 threads, 8x8 register tile per thread.
// ---------------------------------------------------------------------------
__global__ __launch_bounds__(256) void gemm_nt_bias(
    const float* __restrict__ A, const float* __restrict__ B,
    const float* __restrict__ bias, float* __restrict__ C,
    int M, int N, int K, float scale)
{
    __shared__ float As[16][132];   // [k][m], pad 4 to break store conflicts
    __shared__ float Bs[16][132];   // [k][n]

    const int tid = threadIdx.x;
    const int tx = tid & 15;
    const int ty = tid >> 4;
    const int bm = blockIdx.y * 128;
    const int bn = blockIdx.x * 128;

    float acc[8][8];
#pragma unroll
    for (int i = 0; i < 8; i++)
#pragma unroll
        for (int j = 0; j < 8; j++) acc[i][j] = 0.0f;

    const int r_ld  = tid >> 2;        // 0..63
    const int kq_ld = (tid & 3) << 2;  // 0,4,8,12

    for (int k0 = 0; k0 < K; k0 += 16) {
#pragma unroll
        for (int l = 0; l < 2; l++) {
            int r = r_ld + l * 64;
            float4 va = *reinterpret_cast<const float4*>(A + (size_t)(bm + r) * K + k0 + kq_ld);
            As[kq_ld + 0][r] = va.x;
            As[kq_ld + 1][r] = va.y;
            As[kq_ld + 2][r] = va.z;
            As[kq_ld + 3][r] = va.w;
            float4 vb = *reinterpret_cast<const float4*>(B + (size_t)(bn + r) * K + k0 + kq_ld);
            Bs[kq_ld + 0][r] = vb.x;
            Bs[kq_ld + 1][r] = vb.y;
            Bs[kq_ld + 2][r] = vb.z;
            Bs[kq_ld + 3][r] = vb.w;
        }
        __syncthreads();

#pragma unroll
        for (int kk = 0; kk < 16; kk++) {
            float a[8], b[8];
            float4 t0 = *reinterpret_cast<const float4*>(&As[kk][ty * 8]);
            float4 t1 = *reinterpret_cast<const float4*>(&As[kk][ty * 8 + 4]);
            float4 t2 = *reinterpret_cast<const float4*>(&Bs[kk][tx * 8]);
            float4 t3 = *reinterpret_cast<const float4*>(&Bs[kk][tx * 8 + 4]);
            a[0] = t0.x; a[1] = t0.y; a[2] = t0.z; a[3] = t0.w;
            a[4] = t1.x; a[5] = t1.y; a[6] = t1.z; a[7] = t1.w;
            b[0] = t2.x; b[1] = t2.y; b[2] = t2.z; b[3] = t2.w;
            b[4] = t3.x; b[5] = t3.y; b[6] = t3.z; b[7] = t3.w;
#pragma unroll
            for (int i = 0; i < 8; i++)
#pragma unroll
                for (int j = 0; j < 8; j++)
                    acc[i][j] = fmaf(a[i], b[j], acc[i][j]);
        }
        __syncthreads();
    }

    float bb[8];
#pragma unroll
    for (int j = 0; j < 8; j++) bb[j] = bias[bn + tx * 8 + j];

#pragma unroll
    for (int i = 0; i < 8; i++) {
        float4 o0, o1;
        o0.x = (acc[i][0] + bb[0]) * scale;
        o0.y = (acc[i][1] + bb[1]) * scale;
        o0.z = (acc[i][2] + bb[2]) * scale;
        o0.w = (acc[i][3] + bb[3]) * scale;
        o1.x = (acc[i][4] + bb[4]) * scale;
        o1.y = (acc[i][5] + bb[5]) * scale;
        o1.z = (acc[i][6] + bb[6]) * scale;
        o1.w = (acc[i][7] + bb[7]) * scale;
        size_t off = (size_t)(bm + ty * 8 + i) * N + bn + tx * 8;
        *reinterpret_cast<float4*>(C + off)     = o0;
        *reinterpret_cast<float4*>(C + off + 4) = o1;
    }
}

// ---------------------------------------------------------------------------
// Attention per (h, c): S = q k^T (q pre-scaled), mask, softmax, probs out,
// ctx = P v.  One block per (c, h); 256 threads.
// Smem: ps[128][130] (also hosts qs[128][65] in phase 1),
//       kst[64][132] transposed K (also hosts vs[128][64] in phase 2).
// ---------------------------------------------------------------------------
#define PS_LD  130
#define KST_LD 132
#define ATTN_SMEM_BYTES ((128 * PS_LD + 64 * KST_LD) * 4)   // 100352

__global__ __launch_bounds__(256) void attn_kernel(
    const float* __restrict__ q, const float* __restrict__ k, const float* __restrict__ v,
    const unsigned char* __restrict__ mask,
    float* __restrict__ probs, float* __restrict__ ctx, int write_probs)
{
    extern __shared__ float sm[];
    float* ps  = sm;                  // [128][130]
    float* qs  = sm;                  // [128][65] (inside ps region, phase 1 only)
    float* kst = sm + 128 * PS_LD;    // [64][132] transposed K
    float* vs  = kst;                 // [128][64] in phase 2

    const int c  = blockIdx.x;        // 0..255
    const int h  = blockIdx.y;        // 0..11
    const int tid = threadIdx.x;
    const int tx = tid & 15;
    const int ty = tid >> 4;

    // ---- load q (row-major, pad 65) and k (transposed, pad 132) ----
#pragma unroll
    for (int l = 0; l < 32; l++) {
        int idx = tid + l * 256;      // 0..8191
        int d = idx & 63;
        int i = idx >> 6;
        size_t goff = ((size_t)i * 256 + c) * 768 + h * 64 + d;
        qs[i * 65 + d]       = q[goff];
        kst[d * KST_LD + i]  = k[goff];
    }
    __syncthreads();

    // ---- phase 1: S[i][j], thread owns rows ty*8.., cols tx*8.. ----
    float acc[8][8];
#pragma unroll
    for (int i = 0; i < 8; i++)
#pragma unroll
        for (int j = 0; j < 8; j++) acc[i][j] = 0.0f;

#pragma unroll 4
    for (int d = 0; d < 64; d++) {
        float a[8], b[8];
#pragma unroll
        for (int ii = 0; ii < 8; ii++) a[ii] = qs[(ty * 8 + ii) * 65 + d];
        float4 t0 = *reinterpret_cast<const float4*>(&kst[d * KST_LD + tx * 8]);
        float4 t1 = *reinterpret_cast<const float4*>(&kst[d * KST_LD + tx * 8 + 4]);
        b[0] = t0.x; b[1] = t0.y; b[2] = t0.z; b[3] = t0.w;
        b[4] = t1.x; b[5] = t1.y; b[6] = t1.z; b[7] = t1.w;
#pragma unroll
        for (int ii = 0; ii < 8; ii++)
#pragma unroll
            for (int jj = 0; jj < 8; jj++)
                acc[ii][jj] = fmaf(a[ii], b[jj], acc[ii][jj]);
    }

    // ---- padding mask: mask[b=0, j, c] over the j (key) axis ----
#pragma unroll
    for (int jj = 0; jj < 8; jj++) {
        int j = tx * 8 + jj;
        if (mask[(size_t)j * 256 + c]) {
#pragma unroll
            for (int ii = 0; ii < 8; ii++) acc[ii][jj] = -10000.0f;
        }
    }

    // ---- softmax over j: each row lives in one 16-lane (tx) group ----
#pragma unroll
    for (int ii = 0; ii < 8; ii++) {
        float m = acc[ii][0];
#pragma unroll
        for (int jj = 1; jj < 8; jj++) m = fmaxf(m, acc[ii][jj]);
#pragma unroll
        for (int s = 1; s <= 8; s <<= 1)
            m = fmaxf(m, __shfl_xor_sync(0xffffffffu, m, s));
        float ssum = 0.0f;
#pragma unroll
        for (int jj = 0; jj < 8; jj++) {
            float e = __expf(acc[ii][jj] - m);
            acc[ii][jj] = e;
            ssum += e;
        }
#pragma unroll
        for (int s = 1; s <= 8; s <<= 1)
            ssum += __shfl_xor_sync(0xffffffffu, ssum, s);
        float inv = 1.0f / ssum;
#pragma unroll
        for (int jj = 0; jj < 8; jj++) acc[ii][jj] *= inv;
    }

    __syncthreads();   // done reading qs / kst

    // ---- stage P to smem, emit probs, load V ----
#pragma unroll
    for (int ii = 0; ii < 8; ii++) {
        int i = ty * 8 + ii;
#pragma unroll
        for (int jj = 0; jj < 8; jj++)
            ps[i * PS_LD + tx * 8 + jj] = acc[ii][jj];
        if (write_probs) {
            float4 p0 = make_float4(acc[ii][0], acc[ii][1], acc[ii][2], acc[ii][3]);
            float4 p1 = make_float4(acc[ii][4], acc[ii][5], acc[ii][6], acc[ii][7]);
            size_t poff = (((size_t)h * 256 + c) * 128 + i) * 128 + tx * 8;
            *reinterpret_cast<float4*>(probs + poff)     = p0;
            *reinterpret_cast<float4*>(probs + poff + 4) = p1;
        }
    }
#pragma unroll
    for (int l = 0; l < 8; l++) {
        int idx = tid + l * 256;      // 0..2047 float4s
        int i = idx >> 4;
        int d4 = (idx & 15) * 4;
        *reinterpret_cast<float4*>(&vs[i * 64 + d4]) =
            *reinterpret_cast<const float4*>(&v[((size_t)i * 256 + c) * 768 + h * 64 + d4]);
    }
    __syncthreads();

    // ---- phase 2: ctx[i][d] = sum_j P[i][j] v[j][d]; thread: 8 rows x 4 d ----
    float acc2[8][4];
#pragma unroll
    for (int i = 0; i < 8; i++)
#pragma unroll
        for (int j = 0; j < 4; j++) acc2[i][j] = 0.0f;

#pragma unroll 4
    for (int j = 0; j < 128; j++) {
        float a[8];
#pragma unroll
        for (int ii = 0; ii < 8; ii++) a[ii] = ps[(ty * 8 + ii) * PS_LD + j];
        float4 bv = *reinterpret_cast<const float4*>(&vs[j * 64 + tx * 4]);
#pragma unroll
        for (int ii = 0; ii < 8; ii++) {
            acc2[ii][0] = fmaf(a[ii], bv.x, acc2[ii][0]);
            acc2[ii][1] = fmaf(a[ii], bv.y, acc2[ii][1]);
            acc2[ii][2] = fmaf(a[ii], bv.z, acc2[ii][2]);
            acc2[ii][3] = fmaf(a[ii], bv.w, acc2[ii][3]);
        }
    }

#pragma unroll
    for (int ii = 0; ii < 8; ii++) {
        int i = ty * 8 + ii;
        float4 o = make_float4(acc2[ii][0], acc2[ii][1], acc2[ii][2], acc2[ii][3]);
        *reinterpret_cast<float4*>(&ctx[((size_t)i * 256 + c) * 768 + h * 64 + tx * 4]) = o;
    }
}

// ---------------------------------------------------------------------------
extern "C" void kernel_launch(void* const* d_in, const int* in_sizes, int n_in,
                              void* d_out, int out_size)
{
    const float*         x     = (const float*)d_in[0];
    const unsigned char* pmask = (const unsigned char*)d_in[1];
    const float* Wq = (const float*)d_in[2];
    const float* bq = (const float*)d_in[3];
    const float* Wk = (const float*)d_in[4];
    const float* bk = (const float*)d_in[5];
    const float* Wv = (const float*)d_in[6];
    const float* bv = (const float*)d_in[7];
    const float* Wo = (const float*)d_in[8];
    const float* bo = (const float*)d_in[9];

    float *pq, *pk, *pv, *pctx;
    cudaGetSymbolAddress((void**)&pq,  g_q);
    cudaGetSymbolAddress((void**)&pk,  g_k);
    cudaGetSymbolAddress((void**)&pv,  g_v);
    cudaGetSymbolAddress((void**)&pctx, g_ctx);

    float* out = (float*)d_out;
    float* out_ptr   = out;
    float* probs_ptr = nullptr;
    int    do_out    = 1;
    long   os        = (long)out_size;
    if (os >= OUT_ELEMS + PROBS_ELEMS) {
        probs_ptr = out + OUT_ELEMS;           // [output ; probs]
    } else if (os == PROBS_ELEMS) {
        probs_ptr = out;                       // probs only
        do_out = 0;
    }                                          // else: output only

    const int M = 32768, N = 768, K = 768;
    dim3 ggrid(N / 128, M / 128);              // (6, 256)

    gemm_nt_bias<<<ggrid, 256>>>(x, Wq, bq, pq, M, N, K, 0.125f);   // 64^-0.5
    gemm_nt_bias<<<ggrid, 256>>>(x, Wk, bk, pk, M, N, K, 1.0f);
    gemm_nt_bias<<<ggrid, 256>>>(x, Wv, bv, pv, M, N, K, 1.0f);

    cudaFuncSetAttribute(attn_kernel, cudaFuncAttributeMaxDynamicSharedMemorySize,
                         ATTN_SMEM_BYTES);
    attn_kernel<<<dim3(256, 12), 256, ATTN_SMEM_BYTES>>>(
        pq, pk, pv, pmask, probs_ptr, pctx, probs_ptr != nullptr ? 1 : 0);

    if (do_out)
        gemm_nt_bias<<<ggrid, 256>>>(pctx, Wo, bo, out_ptr, M, N, K, 1.0f);
}

// round 3
// speedup vs baseline: 2.7204x; 2.7204x over previous
#include <cuda_runtime.h>
#include <cstdint>

#define OUT_ELEMS   25165824L   // 128*256*768
#define PROBS_ELEMS 50331648L   // 12*256*128*128

// Scratch (allocation-free rule: device globals)
__device__ float g_q[25165824];
__device__ float g_k[25165824];
__device__ float g_v[25165824];
__device__ float g_ctx[25165824];
__device__ float g_xr[25165824];
__device__ float g_wr[4][589824];

// ---------------------------------------------------------------------------
// Helpers
// ---------------------------------------------------------------------------
__device__ __forceinline__ uint32_t smem_u32(const void* p) {
    uint32_t a;
    asm("{ .reg .u64 t; cvta.to.shared.u64 t, %1; cvt.u32.u64 %0, t; }" : "=r"(a) : "l"(p));
    return a;
}
__device__ __forceinline__ float tf32r(float x) {
    float y; asm("cvt.rna.tf32.f32 %0, %1;" : "=f"(y) : "f"(x)); return y;
}
__device__ __forceinline__ void cp16(uint32_t s, const void* g) {
    asm volatile("cp.async.cg.shared.global [%0], [%1], 16;"
        :: "r"(s), "l"((unsigned long long)__cvta_generic_to_global(g)) : "memory");
}
__device__ __forceinline__ void mma1688(float (&d)[4], const uint32_t (&a)[4], const uint32_t (&b)[2]) {
    asm volatile(
        "mma.sync.aligned.m16n8k8.row.col.f32.tf32.tf32.f32 "
        "{%0,%1,%2,%3}, {%4,%5,%6,%7}, {%8,%9}, {%0,%1,%2,%3};"
        : "+f"(d[0]), "+f"(d[1]), "+f"(d[2]), "+f"(d[3])
        : "r"(a[0]), "r"(a[1]), "r"(a[2]), "r"(a[3]), "r"(b[0]), "r"(b[1]));
}

// ---------------------------------------------------------------------------
// tf32 mma.sync NT-GEMM:  C[m,n] = (sum_k A[m,k]*B[n,k] + bias[n]) * scale
// A [M,K], B [N,K] row-major, both tf32-pre-rounded fp32.
// BM=128 BN=128 BK=32, 256 thr, warp grid 4(m)x2(n), warp tile 32x64.
// Smem: A [128][36], B [128][36] per stage; 2-stage cp.async double buffer.
// ---------------------------------------------------------------------------
#define LDA      36
#define A_FLOATS (128 * LDA)        // 4608
#define STAGE_F  (2 * A_FLOATS)     // 9216 floats (A+B)
#define GEMM_SMEM (2 * STAGE_F * 4) // 73728 bytes
#define NT 24                       // K=768 / 32

__device__ __forceinline__ void load_stage(
    float* stg, const float* Ab, const float* Bb, int K, int k0, int tid)
{
#pragma unroll
    for (int i = 0; i < 4; i++) {
        int q  = tid + i * 256;     // 0..1023
        int r  = q >> 3;            // row 0..127
        int cc = q & 7;             // 16B chunk
        cp16(smem_u32(stg + r * LDA + cc * 4),            Ab + (long)r * K + k0 + cc * 4);
        cp16(smem_u32(stg + A_FLOATS + r * LDA + cc * 4), Bb + (long)r * K + k0 + cc * 4);
    }
    asm volatile("cp.async.commit_group;" ::: "memory");
}

__global__ __launch_bounds__(256, 2) void gemm_mma(
    const float* __restrict__ A, const float* __restrict__ B,
    const float* __restrict__ bias, float* __restrict__ C,
    int M, int N, int K, float scale)
{
    extern __shared__ float sm[];

    const int tid  = threadIdx.x;
    const int wid  = tid >> 5;
    const int lane = tid & 31;
    const int g    = lane >> 2;     // groupID 0..7
    const int tg   = lane & 3;      // thread-in-group 0..3
    const int wm   = wid >> 1;      // 0..3 -> m offset wm*32
    const int wn   = wid & 1;       // 0..1 -> n offset wn*64
    const long bm  = (long)blockIdx.y * 128;
    const long bn  = (long)blockIdx.x * 128;

    const float* Ab = A + bm * K;
    const float* Bb = B + bn * K;

    float acc[2][8][4];
#pragma unroll
    for (int mf = 0; mf < 2; mf++)
#pragma unroll
        for (int nf = 0; nf < 8; nf++)
#pragma unroll
            for (int r = 0; r < 4; r++) acc[mf][nf][r] = 0.0f;

    load_stage(sm, Ab, Bb, K, 0, tid);

    const int a_base0 = (wm * 32 + g) * LDA + tg;       // + mf*16*LDA
    const int b_base0 = (wn * 64 + g) * LDA + tg;       // + nf*8*LDA

    for (int kt = 0; kt < NT; kt++) {
        if (kt < NT - 1)
            load_stage(sm + ((kt + 1) & 1) * STAGE_F, Ab, Bb, K, (kt + 1) * 32, tid);
        if (kt < NT - 1) asm volatile("cp.async.wait_group 1;" ::: "memory");
        else             asm volatile("cp.async.wait_group 0;" ::: "memory");
        __syncthreads();

        const uint32_t* uA = reinterpret_cast<const uint32_t*>(sm + (kt & 1) * STAGE_F);
        const uint32_t* uB = uA + A_FLOATS;

#pragma unroll
        for (int t = 0; t < 4; t++) {
            const int k0 = t * 8;
            uint32_t a[2][4], b[8][2];
#pragma unroll
            for (int mf = 0; mf < 2; mf++) {
                int ab = a_base0 + mf * 16 * LDA + k0;
                a[mf][0] = uA[ab];
                a[mf][1] = uA[ab + 8 * LDA];
                a[mf][2] = uA[ab + 4];
                a[mf][3] = uA[ab + 8 * LDA + 4];
            }
#pragma unroll
            for (int nf = 0; nf < 8; nf++) {
                int bb = b_base0 + nf * 8 * LDA + k0;
                b[nf][0] = uB[bb];
                b[nf][1] = uB[bb + 4];
            }
#pragma unroll
            for (int mf = 0; mf < 2; mf++)
#pragma unroll
                for (int nf = 0; nf < 8; nf++)
                    mma1688(acc[mf][nf], a[mf], b[nf]);
        }
        __syncthreads();
    }

    // -------- epilogue: (acc + bias) * scale --------
#pragma unroll
    for (int mf = 0; mf < 2; mf++) {
        long row0 = bm + wm * 32 + mf * 16 + g;
#pragma unroll
        for (int nf = 0; nf < 8; nf++) {
            int col = (int)bn + wn * 64 + nf * 8 + tg * 2;
            float b0 = bias[col], b1 = bias[col + 1];
            float2 o0 = make_float2((acc[mf][nf][0] + b0) * scale,
                                    (acc[mf][nf][1] + b1) * scale);
            float2 o1 = make_float2((acc[mf][nf][2] + b0) * scale,
                                    (acc[mf][nf][3] + b1) * scale);
            *reinterpret_cast<float2*>(C + row0 * N + col)       = o0;
            *reinterpret_cast<float2*>(C + (row0 + 8) * N + col) = o1;
        }
    }
}

// ---------------------------------------------------------------------------
// tf32 pre-rounding passes
// ---------------------------------------------------------------------------
__global__ void round_x_k(const float4* __restrict__ in, float4* __restrict__ out, int n4)
{
    int i = blockIdx.x * blockDim.x + threadIdx.x;
    if (i < n4) {
        float4 v = in[i];
        v.x = tf32r(v.x); v.y = tf32r(v.y); v.z = tf32r(v.z); v.w = tf32r(v.w);
        out[i] = v;
    }
}

__global__ void round_w_k(const float4* __restrict__ w0, const float4* __restrict__ w1,
                          const float4* __restrict__ w2, const float4* __restrict__ w3,
                          float4* __restrict__ o)
{
    const float4* in = (blockIdx.y == 0) ? w0 : (blockIdx.y == 1) ? w1 :
                       (blockIdx.y == 2) ? w2 : w3;
    float4* out = o + (size_t)blockIdx.y * 147456;
    int i = blockIdx.x * blockDim.x + threadIdx.x;   // 576*256 = 147456
    float4 v = in[i];
    v.x = tf32r(v.x); v.y = tf32r(v.y); v.z = tf32r(v.z); v.w = tf32r(v.w);
    out[i] = v;
}

// ---------------------------------------------------------------------------
// Attention per (h, c) — fp32 SIMT (R1), ctx tf32-rounded on store.
// ---------------------------------------------------------------------------
#define PS_LD  130
#define KST_LD 132
#define ATTN_SMEM_BYTES ((128 * PS_LD + 64 * KST_LD) * 4)   // 100352

__global__ __launch_bounds__(256) void attn_kernel(
    const float* __restrict__ q, const float* __restrict__ k, const float* __restrict__ v,
    const unsigned char* __restrict__ mask,
    float* __restrict__ probs, float* __restrict__ ctx, int write_probs)
{
    extern __shared__ float smf[];
    float* ps  = smf;
    float* qs  = smf;
    float* kst = smf + 128 * PS_LD;
    float* vs  = kst;

    const int c  = blockIdx.x;
    const int h  = blockIdx.y;
    const int tid = threadIdx.x;
    const int tx = tid & 15;
    const int ty = tid >> 4;

#pragma unroll
    for (int l = 0; l < 32; l++) {
        int idx = tid + l * 256;
        int d = idx & 63;
        int i = idx >> 6;
        size_t goff = ((size_t)i * 256 + c) * 768 + h * 64 + d;
        qs[i * 65 + d]       = q[goff];
        kst[d * KST_LD + i]  = k[goff];
    }
    __syncthreads();

    float acc[8][8];
#pragma unroll
    for (int i = 0; i < 8; i++)
#pragma unroll
        for (int j = 0; j < 8; j++) acc[i][j] = 0.0f;

#pragma unroll 4
    for (int d = 0; d < 64; d++) {
        float a[8], b[8];
#pragma unroll
        for (int ii = 0; ii < 8; ii++) a[ii] = qs[(ty * 8 + ii) * 65 + d];
        float4 t0 = *reinterpret_cast<const float4*>(&kst[d * KST_LD + tx * 8]);
        float4 t1 = *reinterpret_cast<const float4*>(&kst[d * KST_LD + tx * 8 + 4]);
        b[0] = t0.x; b[1] = t0.y; b[2] = t0.z; b[3] = t0.w;
        b[4] = t1.x; b[5] = t1.y; b[6] = t1.z; b[7] = t1.w;
#pragma unroll
        for (int ii = 0; ii < 8; ii++)
#pragma unroll
            for (int jj = 0; jj < 8; jj++)
                acc[ii][jj] = fmaf(a[ii], b[jj], acc[ii][jj]);
    }

#pragma unroll
    for (int jj = 0; jj < 8; jj++) {
        int j = tx * 8 + jj;
        if (mask[(size_t)j * 256 + c]) {
#pragma unroll
            for (int ii = 0; ii < 8; ii++) acc[ii][jj] = -10000.0f;
        }
    }

#pragma unroll
    for (int ii = 0; ii < 8; ii++) {
        float m = acc[ii][0];
#pragma unroll
        for (int jj = 1; jj < 8; jj++) m = fmaxf(m, acc[ii][jj]);
#pragma unroll
        for (int s = 1; s <= 8; s <<= 1)
            m = fmaxf(m, __shfl_xor_sync(0xffffffffu, m, s));
        float ssum = 0.0f;
#pragma unroll
        for (int jj = 0; jj < 8; jj++) {
            float e = __expf(acc[ii][jj] - m);
            acc[ii][jj] = e;
            ssum += e;
        }
#pragma unroll
        for (int s = 1; s <= 8; s <<= 1)
            ssum += __shfl_xor_sync(0xffffffffu, ssum, s);
        float inv = 1.0f / ssum;
#pragma unroll
        for (int jj = 0; jj < 8; jj++) acc[ii][jj] *= inv;
    }

    __syncthreads();

#pragma unroll
    for (int ii = 0; ii < 8; ii++) {
        int i = ty * 8 + ii;
#pragma unroll
        for (int jj = 0; jj < 8; jj++)
            ps[i * PS_LD + tx * 8 + jj] = acc[ii][jj];
        if (write_probs) {
            float4 p0 = make_float4(acc[ii][0], acc[ii][1], acc[ii][2], acc[ii][3]);
            float4 p1 = make_float4(acc[ii][4], acc[ii][5], acc[ii][6], acc[ii][7]);
            size_t poff = (((size_t)h * 256 + c) * 128 + i) * 128 + tx * 8;
            *reinterpret_cast<float4*>(probs + poff)     = p0;
            *reinterpret_cast<float4*>(probs + poff + 4) = p1;
        }
    }
#pragma unroll
    for (int l = 0; l < 8; l++) {
        int idx = tid + l * 256;
        int i = idx >> 4;
        int d4 = (idx & 15) * 4;
        *reinterpret_cast<float4*>(&vs[i * 64 + d4]) =
            *reinterpret_cast<const float4*>(&v[((size_t)i * 256 + c) * 768 + h * 64 + d4]);
    }
    __syncthreads();

    float acc2[8][4];
#pragma unroll
    for (int i = 0; i < 8; i++)
#pragma unroll
        for (int j = 0; j < 4; j++) acc2[i][j] = 0.0f;

#pragma unroll 4
    for (int j = 0; j < 128; j++) {
        float a[8];
#pragma unroll
        for (int ii = 0; ii < 8; ii++) a[ii] = ps[(ty * 8 + ii) * PS_LD + j];
        float4 bv = *reinterpret_cast<const float4*>(&vs[j * 64 + tx * 4]);
#pragma unroll
        for (int ii = 0; ii < 8; ii++) {
            acc2[ii][0] = fmaf(a[ii], bv.x, acc2[ii][0]);
            acc2[ii][1] = fmaf(a[ii], bv.y, acc2[ii][1]);
            acc2[ii][2] = fmaf(a[ii], bv.z, acc2[ii][2]);
            acc2[ii][3] = fmaf(a[ii], bv.w, acc2[ii][3]);
        }
    }

#pragma unroll
    for (int ii = 0; ii < 8; ii++) {
        int i = ty * 8 + ii;
        float4 o = make_float4(tf32r(acc2[ii][0]), tf32r(acc2[ii][1]),
                               tf32r(acc2[ii][2]), tf32r(acc2[ii][3]));
        *reinterpret_cast<float4*>(&ctx[((size_t)i * 256 + c) * 768 + h * 64 + tx * 4]) = o;
    }
}

// ---------------------------------------------------------------------------
extern "C" void kernel_launch(void* const* d_in, const int* in_sizes, int n_in,
                              void* d_out, int out_size)
{
    const float*         x     = (const float*)d_in[0];
    const unsigned char* pmask = (const unsigned char*)d_in[1];
    const float* bq = (const float*)d_in[3];
    const float* bk = (const float*)d_in[5];
    const float* bv = (const float*)d_in[7];
    const float* bo = (const float*)d_in[9];

    float *pq, *pk, *pv, *pctx, *pxr, *pwr;
    cudaGetSymbolAddress((void**)&pq,   g_q);
    cudaGetSymbolAddress((void**)&pk,   g_k);
    cudaGetSymbolAddress((void**)&pv,   g_v);
    cudaGetSymbolAddress((void**)&pctx, g_ctx);
    cudaGetSymbolAddress((void**)&pxr,  g_xr);
    cudaGetSymbolAddress((void**)&pwr,  g_wr);

    float* out = (float*)d_out;
    float* out_ptr   = out;
    float* probs_ptr = nullptr;
    int    do_out    = 1;
    long   os        = (long)out_size;
    if (os >= OUT_ELEMS + PROBS_ELEMS) {
        probs_ptr = out + OUT_ELEMS;
    } else if (os == PROBS_ELEMS) {
        probs_ptr = out;
        do_out = 0;
    }

    cudaFuncSetAttribute(gemm_mma, cudaFuncAttributeMaxDynamicSharedMemorySize, GEMM_SMEM);
    cudaFuncSetAttribute(attn_kernel, cudaFuncAttributeMaxDynamicSharedMemorySize,
                         ATTN_SMEM_BYTES);

    // tf32 pre-rounding (rna) of GEMM inputs
    round_x_k<<<24576, 256>>>((const float4*)x, (float4*)pxr, 6291456);
    round_w_k<<<dim3(576, 4), 256>>>((const float4*)d_in[2], (const float4*)d_in[4],
                                     (const float4*)d_in[6], (const float4*)d_in[8],
                                     (float4*)pwr);

    const int M = 32768, N = 768, K = 768;
    dim3 gg(6, 256);   // (N/128, M/128)

    gemm_mma<<<gg, 256, GEMM_SMEM>>>(pxr, pwr + 0 * 589824, bq, pq, M, N, K, 0.125f);
    gemm_mma<<<gg, 256, GEMM_SMEM>>>(pxr, pwr + 1 * 589824, bk, pk, M, N, K, 1.0f);
    gemm_mma<<<gg, 256, GEMM_SMEM>>>(pxr, pwr + 2 * 589824, bv, pv, M, N, K, 1.0f);

    attn_kernel<<<dim3(256, 12), 256, ATTN_SMEM_BYTES>>>(
        pq, pk, pv, pmask, probs_ptr, pctx, probs_ptr != nullptr ? 1 : 0);

    if (do_out)
        gemm_mma<<<gg, 256, GEMM_SMEM>>>(pctx, pwr + 3 * 589824, bo, out_ptr, M, N, K, 1.0f);
}

// round 4
// speedup vs baseline: 3.2809x; 1.2060x over previous
#include <cuda_runtime.h>
#include <cstdint>

#define OUT_ELEMS   25165824L   // 128*256*768
#define PROBS_ELEMS 50331648L   // 12*256*128*128

// Scratch (allocation-free rule: device globals)
__device__ float g_q[25165824];
__device__ float g_k[25165824];
__device__ float g_v[25165824];
__device__ float g_ctx[25165824];
__device__ float g_xr[25165824];
__device__ float g_wr[4][589824];   // rounded Wq,Wk,Wv,Wo; [0..2] = fused [2304,768]

// ---------------------------------------------------------------------------
// Helpers
// ---------------------------------------------------------------------------
__device__ __forceinline__ uint32_t smem_u32(const void* p) {
    uint32_t a;
    asm("{ .reg .u64 t; cvta.to.shared.u64 t, %1; cvt.u32.u64 %0, t; }" : "=r"(a) : "l"(p));
    return a;
}
__device__ __forceinline__ float tf32r(float x) {
    float y; asm("cvt.rna.tf32.f32 %0, %1;" : "=f"(y) : "f"(x)); return y;
}
__device__ __forceinline__ void cp16(uint32_t s, const void* g) {
    asm volatile("cp.async.cg.shared.global [%0], [%1], 16;"
        :: "r"(s), "l"((unsigned long long)__cvta_generic_to_global(g)) : "memory");
}
__device__ __forceinline__ void mma1688(float (&d)[4], const uint32_t (&a)[4], const uint32_t (&b)[2]) {
    asm volatile(
        "mma.sync.aligned.m16n8k8.row.col.f32.tf32.tf32.f32 "
        "{%0,%1,%2,%3}, {%4,%5,%6,%7}, {%8,%9}, {%0,%1,%2,%3};"
        : "+f"(d[0]), "+f"(d[1]), "+f"(d[2]), "+f"(d[3])
        : "r"(a[0]), "r"(a[1]), "r"(a[2]), "r"(a[3]), "r"(b[0]), "r"(b[1]));
}

// ---------------------------------------------------------------------------
// tf32 mma.sync NT-GEMM, 3-stage cp.async, single sync per k-tile.
// A [M,768] row-major; B fused [nparts*768, 768] row-major; N_out = 768 per part.
// part = blockIdx.x/6 selects bias/output; scale applied for part 0 only.
// BM=BN=128, BK=32, 256 thr, warp 4m x 2n, warp tile 32x64.
// ---------------------------------------------------------------------------
#define NS 3
#define LDA      36
#define A_FLOATS (128 * LDA)            // 4608
#define STAGE_F  (2 * A_FLOATS)         // 9216 floats (A+B)
#define GEMM_SMEM (NS * STAGE_F * 4)    // 110592 bytes
#define NT 24                           // K=768/32

__device__ __forceinline__ void load_stage(
    float* stg, const float* Ab, const float* Bb, int k0, int tid)
{
#pragma unroll
    for (int i = 0; i < 4; i++) {
        int q  = tid + i * 256;     // 0..1023
        int r  = q >> 3;            // row 0..127
        int cc = q & 7;             // 16B chunk
        cp16(smem_u32(stg + r * LDA + cc * 4),            Ab + (long)r * 768 + k0 + cc * 4);
        cp16(smem_u32(stg + A_FLOATS + r * LDA + cc * 4), Bb + (long)r * 768 + k0 + cc * 4);
    }
    asm volatile("cp.async.commit_group;" ::: "memory");
}

__global__ __launch_bounds__(256, 2) void gemm_mma(
    const float* __restrict__ A, const float* __restrict__ B,
    const float* __restrict__ bias0, const float* __restrict__ bias1,
    const float* __restrict__ bias2,
    float* __restrict__ C0, float* __restrict__ C1, float* __restrict__ C2,
    float s0, int do_round)
{
    extern __shared__ float sm[];

    const int tid  = threadIdx.x;
    const int wid  = tid >> 5;
    const int lane = tid & 31;
    const int g    = lane >> 2;
    const int tg   = lane & 3;
    const int wm   = wid >> 1;
    const int wn   = wid & 1;
    const long bm  = (long)blockIdx.y * 128;
    const int part = blockIdx.x / 6;
    const int bn   = (blockIdx.x % 6) * 128;     // col within 768-wide output

    const float* bias = (part == 0) ? bias0 : (part == 1) ? bias1 : bias2;
    float* C          = (part == 0) ? C0    : (part == 1) ? C1    : C2;
    const float scale = (part == 0) ? s0 : 1.0f;

    const float* Ab = A + bm * 768;
    const float* Bb = B + (long)blockIdx.x * 128 * 768;

    float acc[2][8][4];
#pragma unroll
    for (int mf = 0; mf < 2; mf++)
#pragma unroll
        for (int nf = 0; nf < 8; nf++)
#pragma unroll
            for (int r = 0; r < 4; r++) acc[mf][nf][r] = 0.0f;

    load_stage(sm,           Ab, Bb, 0,  tid);
    load_stage(sm + STAGE_F, Ab, Bb, 32, tid);

    const int a_base0 = (wm * 32 + g) * LDA + tg;
    const int b_base0 = (wn * 64 + g) * LDA + tg;

    int s = 0;
    for (int kt = 0; kt < NT; kt++) {
        if (kt < NT - 1) asm volatile("cp.async.wait_group 1;" ::: "memory");
        else             asm volatile("cp.async.wait_group 0;" ::: "memory");
        __syncthreads();

        if (kt + 2 < NT) {
            int sn = (s + 2 >= NS) ? s + 2 - NS : s + 2;
            load_stage(sm + sn * STAGE_F, Ab, Bb, (kt + 2) * 32, tid);
        }

        const uint32_t* uA = reinterpret_cast<const uint32_t*>(sm + s * STAGE_F);
        const uint32_t* uB = uA + A_FLOATS;

#pragma unroll
        for (int t = 0; t < 4; t++) {
            const int k0 = t * 8;
            uint32_t a[2][4], b[8][2];
#pragma unroll
            for (int mf = 0; mf < 2; mf++) {
                int ab = a_base0 + mf * 16 * LDA + k0;
                a[mf][0] = uA[ab];
                a[mf][1] = uA[ab + 8 * LDA];
                a[mf][2] = uA[ab + 4];
                a[mf][3] = uA[ab + 8 * LDA + 4];
            }
#pragma unroll
            for (int nf = 0; nf < 8; nf++) {
                int bb = b_base0 + nf * 8 * LDA + k0;
                b[nf][0] = uB[bb];
                b[nf][1] = uB[bb + 4];
            }
#pragma unroll
            for (int mf = 0; mf < 2; mf++)
#pragma unroll
                for (int nf = 0; nf < 8; nf++)
                    mma1688(acc[mf][nf], a[mf], b[nf]);
        }
        if (++s == NS) s = 0;
    }

    // -------- epilogue --------
#pragma unroll
    for (int mf = 0; mf < 2; mf++) {
        long row0 = bm + wm * 32 + mf * 16 + g;
#pragma unroll
        for (int nf = 0; nf < 8; nf++) {
            int col = bn + wn * 64 + nf * 8 + tg * 2;
            float b0 = bias[col], b1 = bias[col + 1];
            float v0 = (acc[mf][nf][0] + b0) * scale;
            float v1 = (acc[mf][nf][1] + b1) * scale;
            float v2 = (acc[mf][nf][2] + b0) * scale;
            float v3 = (acc[mf][nf][3] + b1) * scale;
            if (do_round) { v0 = tf32r(v0); v1 = tf32r(v1); v2 = tf32r(v2); v3 = tf32r(v3); }
            *reinterpret_cast<float2*>(C + row0 * 768 + col)       = make_float2(v0, v1);
            *reinterpret_cast<float2*>(C + (row0 + 8) * 768 + col) = make_float2(v2, v3);
        }
    }
}

// ---------------------------------------------------------------------------
// tf32 pre-rounding passes
// ---------------------------------------------------------------------------
__global__ void round_x_k(const float4* __restrict__ in, float4* __restrict__ out, int n4)
{
    int i = blockIdx.x * blockDim.x + threadIdx.x;
    if (i < n4) {
        float4 v = in[i];
        v.x = tf32r(v.x); v.y = tf32r(v.y); v.z = tf32r(v.z); v.w = tf32r(v.w);
        out[i] = v;
    }
}

__global__ void round_w_k(const float4* __restrict__ w0, const float4* __restrict__ w1,
                          const float4* __restrict__ w2, const float4* __restrict__ w3,
                          float4* __restrict__ o)
{
    const float4* in = (blockIdx.y == 0) ? w0 : (blockIdx.y == 1) ? w1 :
                       (blockIdx.y == 2) ? w2 : w3;
    float4* out = o + (size_t)blockIdx.y * 147456;
    int i = blockIdx.x * blockDim.x + threadIdx.x;   // 576*256 = 147456
    float4 v = in[i];
    v.x = tf32r(v.x); v.y = tf32r(v.y); v.z = tf32r(v.z); v.w = tf32r(v.w);
    out[i] = v;
}

// ---------------------------------------------------------------------------
// Attention per (h, c) with mma.sync tf32.
// 256 thr, 8 warps; warp w owns rows [w*16, w*16+16).
// Phase 1: S = Q K^T (warp tile 16x128), mask, in-warp softmax.
// P -> smem (tf32-rounded) + probs -> gmem (unrounded, from regs).
// Phase 2: ctx = P V (warp tile 16x64), V transposed in smem.
// ---------------------------------------------------------------------------
#define QK_LD  68
#define PS_LDa 132
#define VT_LD  132
// region1 floats: qs+ks = 2*128*68 = 17408 (ps[128*132]=16896 overlays it)
// region2 floats: vt = 64*132 = 8448
#define ATTN_SMEM ((2 * 128 * QK_LD + 64 * VT_LD) * 4)   // 103424

__global__ __launch_bounds__(256, 2) void attn_mma(
    const float* __restrict__ q, const float* __restrict__ k, const float* __restrict__ v,
    const unsigned char* __restrict__ mask,
    float* __restrict__ probs, float* __restrict__ ctx, int write_probs)
{
    extern __shared__ float sm[];
    float* qs = sm;
    float* ks = sm + 128 * QK_LD;
    float* ps = sm;                      // overlays qs/ks after phase 1
    float* vt = sm + 2 * 128 * QK_LD;
    __shared__ unsigned char mask_s[128];

    const int c   = blockIdx.x;
    const int h   = blockIdx.y;
    const int tid = threadIdx.x;
    const int w    = tid >> 5;
    const int lane = tid & 31;
    const int g    = lane >> 2;
    const int tg   = lane & 3;

    // ---- load Q, K row-major [i][d]; V transposed [d][j]; mask row ----
#pragma unroll
    for (int l = 0; l < 8; l++) {
        int idx = tid + l * 256;         // 2048 float4 chunks
        int i  = idx >> 4;
        int d4 = (idx & 15) * 4;
        size_t go = ((size_t)i * 256 + c) * 768 + h * 64 + d4;
        *reinterpret_cast<float4*>(&qs[i * QK_LD + d4]) =
            *reinterpret_cast<const float4*>(q + go);
        *reinterpret_cast<float4*>(&ks[i * QK_LD + d4]) =
            *reinterpret_cast<const float4*>(k + go);
    }
#pragma unroll
    for (int l = 0; l < 32; l++) {
        int idx = tid + l * 256;         // 8192 scalars
        int d = idx & 63;
        int j = idx >> 6;
        vt[d * VT_LD + j] = v[((size_t)j * 256 + c) * 768 + h * 64 + d];
    }
    if (tid < 128) mask_s[tid] = mask[(size_t)tid * 256 + c];
    __syncthreads();

    // ---- phase 1: S (rows w*16+{g,g+8}, cols nf*8+tg*2+{0,1}) ----
    float acc[16][4];
#pragma unroll
    for (int nf = 0; nf < 16; nf++)
#pragma unroll
        for (int r = 0; r < 4; r++) acc[nf][r] = 0.0f;

    const uint32_t* uq = reinterpret_cast<const uint32_t*>(qs);
    const uint32_t* uk = reinterpret_cast<const uint32_t*>(ks);
    const int a_base = (w * 16 + g) * QK_LD + tg;
    const int b_base = g * QK_LD + tg;

#pragma unroll
    for (int t = 0; t < 8; t++) {
        const int k0 = t * 8;
        uint32_t a[4];
        a[0] = uq[a_base + k0];
        a[1] = uq[a_base + 8 * QK_LD + k0];
        a[2] = uq[a_base + k0 + 4];
        a[3] = uq[a_base + 8 * QK_LD + k0 + 4];
#pragma unroll
        for (int nf = 0; nf < 16; nf++) {
            uint32_t b[2];
            b[0] = uk[b_base + nf * 8 * QK_LD + k0];
            b[1] = uk[b_base + nf * 8 * QK_LD + k0 + 4];
            mma1688(acc[nf], a, b);
        }
    }

    // ---- mask ----
#pragma unroll
    for (int nf = 0; nf < 16; nf++) {
        int j = nf * 8 + tg * 2;
        if (mask_s[j])     { acc[nf][0] = -10000.0f; acc[nf][2] = -10000.0f; }
        if (mask_s[j + 1]) { acc[nf][1] = -10000.0f; acc[nf][3] = -10000.0f; }
    }

    // ---- softmax: rows g (c0,c1) and g+8 (c2,c3); reduce over tg quad ----
    float m0 = -1e30f, m1 = -1e30f;
#pragma unroll
    for (int nf = 0; nf < 16; nf++) {
        m0 = fmaxf(m0, fmaxf(acc[nf][0], acc[nf][1]));
        m1 = fmaxf(m1, fmaxf(acc[nf][2], acc[nf][3]));
    }
    m0 = fmaxf(m0, __shfl_xor_sync(0xffffffffu, m0, 1));
    m0 = fmaxf(m0, __shfl_xor_sync(0xffffffffu, m0, 2));
    m1 = fmaxf(m1, __shfl_xor_sync(0xffffffffu, m1, 1));
    m1 = fmaxf(m1, __shfl_xor_sync(0xffffffffu, m1, 2));
    float s0 = 0.0f, s1 = 0.0f;
#pragma unroll
    for (int nf = 0; nf < 16; nf++) {
        acc[nf][0] = __expf(acc[nf][0] - m0);
        acc[nf][1] = __expf(acc[nf][1] - m0);
        acc[nf][2] = __expf(acc[nf][2] - m1);
        acc[nf][3] = __expf(acc[nf][3] - m1);
        s0 += acc[nf][0] + acc[nf][1];
        s1 += acc[nf][2] + acc[nf][3];
    }
    s0 += __shfl_xor_sync(0xffffffffu, s0, 1);
    s0 += __shfl_xor_sync(0xffffffffu, s0, 2);
    s1 += __shfl_xor_sync(0xffffffffu, s1, 1);
    s1 += __shfl_xor_sync(0xffffffffu, s1, 2);
    float i0 = 1.0f / s0, i1 = 1.0f / s1;
#pragma unroll
    for (int nf = 0; nf < 16; nf++) {
        acc[nf][0] *= i0; acc[nf][1] *= i0;
        acc[nf][2] *= i1; acc[nf][3] *= i1;
    }

    __syncthreads();   // all warps done reading qs/ks

    // ---- P -> smem (rounded); probs -> gmem (unrounded) ----
    const int row0 = w * 16 + g;
    if (write_probs) {
        float* pb = probs + ((size_t)h * 256 + c) * 16384;
#pragma unroll
        for (int nf = 0; nf < 16; nf++) {
            int col = nf * 8 + tg * 2;
            *reinterpret_cast<float2*>(pb + row0 * 128 + col) =
                make_float2(acc[nf][0], acc[nf][1]);
            *reinterpret_cast<float2*>(pb + (row0 + 8) * 128 + col) =
                make_float2(acc[nf][2], acc[nf][3]);
        }
    }
#pragma unroll
    for (int nf = 0; nf < 16; nf++) {
        int col = nf * 8 + tg * 2;
        *reinterpret_cast<float2*>(&ps[row0 * PS_LDa + col]) =
            make_float2(tf32r(acc[nf][0]), tf32r(acc[nf][1]));
        *reinterpret_cast<float2*>(&ps[(row0 + 8) * PS_LDa + col]) =
            make_float2(tf32r(acc[nf][2]), tf32r(acc[nf][3]));
    }
    __syncthreads();

    // ---- phase 2: ctx = P V ----
    float acc2[8][4];
#pragma unroll
    for (int nf = 0; nf < 8; nf++)
#pragma unroll
        for (int r = 0; r < 4; r++) acc2[nf][r] = 0.0f;

    const uint32_t* up = reinterpret_cast<const uint32_t*>(ps);
    const uint32_t* uv = reinterpret_cast<const uint32_t*>(vt);
    const int a_base2 = (w * 16 + g) * PS_LDa + tg;
    const int b_base2 = g * VT_LD + tg;

#pragma unroll
    for (int t = 0; t < 16; t++) {
        const int k0 = t * 8;
        uint32_t a[4];
        a[0] = up[a_base2 + k0];
        a[1] = up[a_base2 + 8 * PS_LDa + k0];
        a[2] = up[a_base2 + k0 + 4];
        a[3] = up[a_base2 + 8 * PS_LDa + k0 + 4];
#pragma unroll
        for (int nf = 0; nf < 8; nf++) {
            uint32_t b[2];
            b[0] = uv[b_base2 + nf * 8 * VT_LD + k0];
            b[1] = uv[b_base2 + nf * 8 * VT_LD + k0 + 4];
            mma1688(acc2[nf], a, b);
        }
    }

    // ---- ctx epilogue (tf32-rounded: feeds O projection) ----
#pragma unroll
    for (int nf = 0; nf < 8; nf++) {
        int d = nf * 8 + tg * 2;
        size_t go0 = ((size_t)row0 * 256 + c) * 768 + h * 64 + d;
        size_t go1 = ((size_t)(row0 + 8) * 256 + c) * 768 + h * 64 + d;
        *reinterpret_cast<float2*>(ctx + go0) =
            make_float2(tf32r(acc2[nf][0]), tf32r(acc2[nf][1]));
        *reinterpret_cast<float2*>(ctx + go1) =
            make_float2(tf32r(acc2[nf][2]), tf32r(acc2[nf][3]));
    }
}

// ---------------------------------------------------------------------------
extern "C" void kernel_launch(void* const* d_in, const int* in_sizes, int n_in,
                              void* d_out, int out_size)
{
    const float*         x     = (const float*)d_in[0];
    const unsigned char* pmask = (const unsigned char*)d_in[1];
    const float* bq = (const float*)d_in[3];
    const float* bk = (const float*)d_in[5];
    const float* bv = (const float*)d_in[7];
    const float* bo = (const float*)d_in[9];

    float *pq, *pk, *pv, *pctx, *pxr, *pwr;
    cudaGetSymbolAddress((void**)&pq,   g_q);
    cudaGetSymbolAddress((void**)&pk,   g_k);
    cudaGetSymbolAddress((void**)&pv,   g_v);
    cudaGetSymbolAddress((void**)&pctx, g_ctx);
    cudaGetSymbolAddress((void**)&pxr,  g_xr);
    cudaGetSymbolAddress((void**)&pwr,  g_wr);

    float* out = (float*)d_out;
    float* out_ptr   = out;
    float* probs_ptr = nullptr;
    int    do_out    = 1;
    long   os        = (long)out_size;
    if (os >= OUT_ELEMS + PROBS_ELEMS) {
        probs_ptr = out + OUT_ELEMS;
    } else if (os == PROBS_ELEMS) {
        probs_ptr = out;
        do_out = 0;
    }

    cudaFuncSetAttribute(gemm_mma, cudaFuncAttributeMaxDynamicSharedMemorySize, GEMM_SMEM);
    cudaFuncSetAttribute(attn_mma, cudaFuncAttributeMaxDynamicSharedMemorySize, ATTN_SMEM);

    // tf32 pre-rounding (rna) of GEMM inputs
    round_x_k<<<24576, 256>>>((const float4*)x, (float4*)pxr, 6291456);
    round_w_k<<<dim3(576, 4), 256>>>((const float4*)d_in[2], (const float4*)d_in[4],
                                     (const float4*)d_in[6], (const float4*)d_in[8],
                                     (float4*)pwr);

    // fused QKV projection: B = [Wq;Wk;Wv] (g_wr[0..2] contiguous), grid (18, 256)
    gemm_mma<<<dim3(18, 256), 256, GEMM_SMEM>>>(
        pxr, pwr, bq, bk, bv, pq, pk, pv, 0.125f, 1);

    attn_mma<<<dim3(256, 12), 256, ATTN_SMEM>>>(
        pq, pk, pv, pmask, probs_ptr, pctx, probs_ptr != nullptr ? 1 : 0);

    // O projection: part 0 only, grid (6, 256)
    if (do_out)
        gemm_mma<<<dim3(6, 256), 256, GEMM_SMEM>>>(
            pctx, pwr + 3 * 589824, bo, bo, bo, out_ptr, out_ptr, out_ptr, 1.0f, 0);
}